// round 1
// baseline (speedup 1.0000x reference)
#include <cuda_runtime.h>
#include <math.h>
#include <float.h>

#define B_N 8192
#define D_N 384
#define H_N 256
#define C_N 6
#define KMAX 16

// ---------------- scratch (static device globals; no runtime alloc) ----------
__device__ float g_sq[B_N];
__device__ int   g_k[B_N];
__device__ float g_h[(size_t)B_N * H_N];
__device__ float g_topv[2 * (size_t)B_N * KMAX];
__device__ int   g_topi[2 * (size_t)B_N * KMAX];
__device__ int   g_idx[(size_t)B_N * KMAX];

// ---------------- K1: sq[i] = ||x_i||^2 ; tau -> k ---------------------------
__global__ void k_sqtau(const float* __restrict__ x,
                        const float* __restrict__ Wtau,
                        const float* __restrict__ btau) {
    int row  = blockIdx.x * 8 + threadIdx.y;
    int lane = threadIdx.x;
    const float* xr = x + (size_t)row * D_N;
    float s = 0.f, t = 0.f;
    for (int i = lane; i < D_N; i += 32) {
        float v = xr[i];
        s = fmaf(v, v, s);
        t = fmaf(v, Wtau[i], t);
    }
    #pragma unroll
    for (int o = 16; o; o >>= 1) {
        s += __shfl_down_sync(0xffffffffu, s, o);
        t += __shfl_down_sync(0xffffffffu, t, o);
    }
    if (lane == 0) {
        g_sq[row] = s;
        float tau = 1.f / (1.f + expf(-(t + btau[0])));
        float kf  = rintf(16.f - 12.f * tau);   // round-half-even == jnp.round
        kf = fminf(fmaxf(kf, 1.f), 16.f);
        g_k[row] = (int)kf;
    }
}

// ---------------- K2: h = relu(x @ W_proj + b_proj) --------------------------
__global__ __launch_bounds__(256) void k_proj(const float* __restrict__ x,
                                              const float* __restrict__ W,
                                              const float* __restrict__ bias) {
    __shared__ float As[16][68];
    __shared__ float Bs[16][68];
    int tid = threadIdx.x, tx = tid & 15, ty = tid >> 4;
    int mb = blockIdx.y * 64, nb = blockIdx.x * 64;
    float acc[4][4] = {};
    for (int kb = 0; kb < D_N; kb += 16) {
        {   // A tile: 64 rows x 16 k
            int r = tid >> 2, kq = (tid & 3) * 4;
            float4 va = *(const float4*)(x + (size_t)(mb + r) * D_N + kb + kq);
            As[kq + 0][r] = va.x; As[kq + 1][r] = va.y;
            As[kq + 2][r] = va.z; As[kq + 3][r] = va.w;
        }
        {   // B tile: 16 k x 64 cols
            int kr = tid >> 4, c = (tid & 15) * 4;
            float4 vb = *(const float4*)(W + (size_t)(kb + kr) * H_N + nb + c);
            *(float4*)&Bs[kr][c] = vb;
        }
        __syncthreads();
        #pragma unroll
        for (int k = 0; k < 16; k++) {
            float a[4], bv[4];
            #pragma unroll
            for (int i = 0; i < 4; i++) a[i] = As[k][ty * 4 + i];
            #pragma unroll
            for (int j = 0; j < 4; j++) bv[j] = Bs[k][tx * 4 + j];
            #pragma unroll
            for (int i = 0; i < 4; i++)
                #pragma unroll
                for (int j = 0; j < 4; j++)
                    acc[i][j] = fmaf(a[i], bv[j], acc[i][j]);
        }
        __syncthreads();
    }
    #pragma unroll
    for (int i = 0; i < 4; i++) {
        int row = mb + ty * 4 + i;
        #pragma unroll
        for (int j = 0; j < 4; j++) {
            int col = nb + tx * 4 + j;
            float v = acc[i][j] + bias[col];
            g_h[(size_t)row * H_N + col] = v > 0.f ? v : 0.f;
        }
    }
}

// ---------------- K3: fused x@x.T + streaming per-row top-16 -----------------
// grid (64 row-tiles, 2 col-halves); 256 threads; BM=BN=128, BK=16, 8x8 micro
__global__ __launch_bounds__(256, 1) void k_nn(const float* __restrict__ x) {
    extern __shared__ float sm[];
    float* shA  = sm;                    // 16*132
    float* shB  = shA + 16 * 132;        // 16*132
    float* sc   = shB + 16 * 132;        // 128*128
    float* tv   = sc + 128 * 128;        // 128*16
    int*   ti   = (int*)(tv + 128 * 16); // 128*16
    float* tmin = (float*)(ti + 128 * 16); // 128
    float* sqc  = tmin + 128;            // 128

    int tid = threadIdx.x, lane = tid & 31, wid = tid >> 5;
    int tx = tid & 15, ty = tid >> 4;
    int mb = blockIdx.x * 128;
    int colbase = blockIdx.y * 4096;

    for (int i = tid; i < 128 * 16; i += 256) { tv[i] = -FLT_MAX; ti[i] = 0x7fffffff; }
    if (tid < 128) tmin[tid] = -FLT_MAX;
    __syncthreads();

    int r0 = tid >> 2, kq = (tid & 3) * 4;

    for (int ct = 0; ct < 32; ct++) {
        int cb = colbase + ct * 128;
        if (tid < 128) sqc[tid] = g_sq[cb + tid];

        float acc[8][8];
        #pragma unroll
        for (int i = 0; i < 8; i++)
            #pragma unroll
            for (int j = 0; j < 8; j++) acc[i][j] = 0.f;

        for (int kb = 0; kb < D_N; kb += 16) {
            {
                float4 va = *(const float4*)(x + (size_t)(mb + r0) * D_N + kb + kq);
                shA[(kq + 0) * 132 + r0] = va.x; shA[(kq + 1) * 132 + r0] = va.y;
                shA[(kq + 2) * 132 + r0] = va.z; shA[(kq + 3) * 132 + r0] = va.w;
                float4 va2 = *(const float4*)(x + (size_t)(mb + r0 + 64) * D_N + kb + kq);
                shA[(kq + 0) * 132 + r0 + 64] = va2.x; shA[(kq + 1) * 132 + r0 + 64] = va2.y;
                shA[(kq + 2) * 132 + r0 + 64] = va2.z; shA[(kq + 3) * 132 + r0 + 64] = va2.w;
                float4 vb = *(const float4*)(x + (size_t)(cb + r0) * D_N + kb + kq);
                shB[(kq + 0) * 132 + r0] = vb.x; shB[(kq + 1) * 132 + r0] = vb.y;
                shB[(kq + 2) * 132 + r0] = vb.z; shB[(kq + 3) * 132 + r0] = vb.w;
                float4 vb2 = *(const float4*)(x + (size_t)(cb + r0 + 64) * D_N + kb + kq);
                shB[(kq + 0) * 132 + r0 + 64] = vb2.x; shB[(kq + 1) * 132 + r0 + 64] = vb2.y;
                shB[(kq + 2) * 132 + r0 + 64] = vb2.z; shB[(kq + 3) * 132 + r0 + 64] = vb2.w;
            }
            __syncthreads();
            #pragma unroll
            for (int k = 0; k < 16; k++) {
                float4 a0 = *(float4*)(shA + k * 132 + ty * 8);
                float4 a1 = *(float4*)(shA + k * 132 + ty * 8 + 4);
                float4 b0 = *(float4*)(shB + k * 132 + tx * 8);
                float4 b1 = *(float4*)(shB + k * 132 + tx * 8 + 4);
                float a[8] = {a0.x, a0.y, a0.z, a0.w, a1.x, a1.y, a1.z, a1.w};
                float bv[8] = {b0.x, b0.y, b0.z, b0.w, b1.x, b1.y, b1.z, b1.w};
                #pragma unroll
                for (int i = 0; i < 8; i++)
                    #pragma unroll
                    for (int j = 0; j < 8; j++)
                        acc[i][j] = fmaf(a[i], bv[j], acc[i][j]);
            }
            __syncthreads();
        }

        // write selection keys v = 2*dot - sq_j (order == -d2)
        #pragma unroll
        for (int i = 0; i < 8; i++) {
            int r = ty * 8 + i;
            float* dst = sc + r * 128 + tx * 8;
            float4 w0, w1;
            w0.x = 2.f * acc[i][0] - sqc[tx * 8 + 0];
            w0.y = 2.f * acc[i][1] - sqc[tx * 8 + 1];
            w0.z = 2.f * acc[i][2] - sqc[tx * 8 + 2];
            w0.w = 2.f * acc[i][3] - sqc[tx * 8 + 3];
            w1.x = 2.f * acc[i][4] - sqc[tx * 8 + 4];
            w1.y = 2.f * acc[i][5] - sqc[tx * 8 + 5];
            w1.z = 2.f * acc[i][6] - sqc[tx * 8 + 6];
            w1.w = 2.f * acc[i][7] - sqc[tx * 8 + 7];
            *(float4*)dst = w0;
            *(float4*)(dst + 4) = w1;
        }
        __syncthreads();

        // streaming top-16: warp w owns rows w*16..w*16+15
        for (int rr = 0; rr < 16; rr++) {
            int r = wid * 16 + rr;
            float m = tmin[r];
            float v0 = sc[r * 128 + lane];
            float v1 = sc[r * 128 + lane + 32];
            float v2 = sc[r * 128 + lane + 64];
            float v3 = sc[r * 128 + lane + 96];
            unsigned p0 = __ballot_sync(0xffffffffu, v0 > m);
            unsigned p1 = __ballot_sync(0xffffffffu, v1 > m);
            unsigned p2 = __ballot_sync(0xffffffffu, v2 > m);
            unsigned p3 = __ballot_sync(0xffffffffu, v3 > m);
            if (lane == 0 && (p0 | p1 | p2 | p3)) {
                float* rv = tv + r * 16;
                int*   rx = ti + r * 16;
                float cm = m;
                unsigned masks[4] = {p0, p1, p2, p3};
                for (int q = 0; q < 4; q++) {
                    unsigned mm = masks[q];
                    while (mm) {
                        int c = __ffs(mm) - 1; mm &= mm - 1;
                        int col = q * 32 + c;
                        float v = sc[r * 128 + col];
                        if (v > cm) {
                            // evict worst: min value; among mins, largest index
                            int slot = 0;
                            for (int s = 1; s < 16; s++) {
                                if (rv[s] < rv[slot] ||
                                    (rv[s] == rv[slot] && rx[s] > rx[slot])) slot = s;
                            }
                            rv[slot] = v; rx[slot] = cb + col;
                            float nm = rv[0];
                            for (int s = 1; s < 16; s++) nm = fminf(nm, rv[s]);
                            cm = nm;
                        }
                    }
                }
                tmin[r] = cm;
            }
        }
        __syncthreads();
    }

    // sort each row's 16 by (v desc, idx asc) and write out
    if (tid < 128) {
        float* rv = tv + tid * 16;
        int*   rx = ti + tid * 16;
        for (int a = 1; a < 16; a++) {
            float v = rv[a]; int id = rx[a]; int b2 = a - 1;
            while (b2 >= 0 && (rv[b2] < v || (rv[b2] == v && rx[b2] > id))) {
                rv[b2 + 1] = rv[b2]; rx[b2 + 1] = rx[b2]; b2--;
            }
            rv[b2 + 1] = v; rx[b2 + 1] = id;
        }
        int row = mb + tid;
        size_t base = ((size_t)blockIdx.y * B_N + row) * KMAX;
        for (int s = 0; s < 16; s++) { g_topv[base + s] = rv[s]; g_topi[base + s] = rx[s]; }
    }
}

// ---------------- K3b: merge the two column-half top-16 lists ----------------
__global__ void k_merge() {
    int row = blockIdx.x * 256 + threadIdx.x;
    if (row >= B_N) return;
    const float* v0 = g_topv + (size_t)row * KMAX;
    const int*   i0 = g_topi + (size_t)row * KMAX;
    const float* v1 = g_topv + ((size_t)B_N + row) * KMAX;
    const int*   i1 = g_topi + ((size_t)B_N + row) * KMAX;
    int a = 0, b = 0;
    int* out = g_idx + (size_t)row * KMAX;
    for (int s = 0; s < 16; s++) {
        bool take0 = (v0[a] > v1[b]) || (v0[a] == v1[b] && i0[a] < i1[b]);
        out[s] = take0 ? i0[a++] : i1[b++];
    }
}

// ---------------- K4: gather-mean -> W_res -> relu -> +h -> LN -> fc ---------
__global__ __launch_bounds__(256) void k_tail(const float* __restrict__ Wres,
                                              const float* __restrict__ bres,
                                              const float* __restrict__ lng,
                                              const float* __restrict__ lnb,
                                              const float* __restrict__ Wfc,
                                              const float* __restrict__ bfc,
                                              float* __restrict__ out) {
    extern __shared__ float sm[];
    float* agg  = sm;                    // 16*256 (later reused as z)
    float* hs   = agg + 16 * H_N;        // 16*256
    float* Ws   = hs + 16 * H_N;         // 32*256
    int*   idxs = (int*)(Ws + 32 * H_N); // 16*16
    int*   ks   = idxs + 16 * 16;        // 16

    int tid = threadIdx.x;
    int rb = blockIdx.x * 16;
    {
        int r = tid >> 4, j = tid & 15;
        idxs[tid] = g_idx[(size_t)(rb + r) * KMAX + j];
    }
    if (tid < 16) ks[tid] = g_k[rb + tid];
    __syncthreads();

    int c = tid;
    for (int r = 0; r < 16; r++) {
        int kr = ks[r];
        float s = 0.f;
        for (int j = 0; j < kr; j++)
            s += g_h[(size_t)idxs[r * 16 + j] * H_N + c];
        agg[r * H_N + c] = s / (float)kr;
        hs[r * H_N + c]  = g_h[(size_t)(rb + r) * H_N + c];
    }
    __syncthreads();

    float acc[16];
    #pragma unroll
    for (int r = 0; r < 16; r++) acc[r] = 0.f;
    for (int kb = 0; kb < H_N; kb += 32) {
        __syncthreads();
        for (int kk = 0; kk < 32; kk++)
            Ws[kk * H_N + c] = Wres[(size_t)(kb + kk) * H_N + c];
        __syncthreads();
        for (int kk = 0; kk < 32; kk++) {
            float w = Ws[kk * H_N + c];
            #pragma unroll
            for (int r = 0; r < 16; r++)
                acc[r] = fmaf(agg[r * H_N + kb + kk], w, acc[r]);
        }
    }
    __syncthreads();

    float brc = bres[c];
    for (int r = 0; r < 16; r++) {
        float rv = acc[r] + brc;
        rv = rv > 0.f ? rv : 0.f;
        agg[r * H_N + c] = hs[r * H_N + c] + rv;   // z
    }
    __syncthreads();

    int lane = tid & 31, wid = tid >> 5;
    for (int rr = 0; rr < 2; rr++) {
        int r = wid * 2 + rr;
        int row = rb + r;
        float* z = agg + r * H_N;
        float s = 0.f;
        #pragma unroll
        for (int t = 0; t < 8; t++) s += z[lane + 32 * t];
        #pragma unroll
        for (int o = 16; o; o >>= 1) s += __shfl_xor_sync(0xffffffffu, s, o);
        float mu = s * (1.f / 256.f);
        float vs = 0.f;
        #pragma unroll
        for (int t = 0; t < 8; t++) {
            float d = z[lane + 32 * t] - mu;
            vs = fmaf(d, d, vs);
        }
        #pragma unroll
        for (int o = 16; o; o >>= 1) vs += __shfl_xor_sync(0xffffffffu, vs, o);
        float rstd = rsqrtf(vs * (1.f / 256.f) + 1e-5f);

        float vals[8];
        #pragma unroll
        for (int t = 0; t < 8; t++) {
            int col = lane + 32 * t;
            float zn = (z[col] - mu) * rstd;
            vals[t] = zn * lng[col] + lnb[col];
        }
        #pragma unroll
        for (int cc = 0; cc < C_N; cc++) {
            float p = 0.f;
            #pragma unroll
            for (int t = 0; t < 8; t++) {
                int col = lane + 32 * t;
                p = fmaf(vals[t], Wfc[(size_t)col * C_N + cc], p);
            }
            #pragma unroll
            for (int o = 16; o; o >>= 1) p += __shfl_xor_sync(0xffffffffu, p, o);
            if (lane == 0) out[(size_t)row * C_N + cc] = p + bfc[cc];
        }
    }
}

// ---------------- launch ------------------------------------------------------
extern "C" void kernel_launch(void* const* d_in, const int* in_sizes, int n_in,
                              void* d_out, int out_size) {
    const float* x  = (const float*)d_in[0];
    const float* Wp = (const float*)d_in[1];
    const float* bp = (const float*)d_in[2];
    const float* Wt = (const float*)d_in[3];
    const float* bt = (const float*)d_in[4];
    const float* Wr = (const float*)d_in[5];
    const float* br = (const float*)d_in[6];
    const float* lg = (const float*)d_in[7];
    const float* lb = (const float*)d_in[8];
    const float* Wf = (const float*)d_in[9];
    const float* bf = (const float*)d_in[10];
    float* out = (float*)d_out;

    const int SMEM_NN   = (2 * 16 * 132 + 128 * 128 + 128 * 16 * 2 + 128 + 128) * 4;
    const int SMEM_TAIL = (16 * 256 * 2 + 32 * 256 + 16 * 16 + 16) * 4;

    cudaFuncSetAttribute(k_nn,   cudaFuncAttributeMaxDynamicSharedMemorySize, SMEM_NN);
    cudaFuncSetAttribute(k_tail, cudaFuncAttributeMaxDynamicSharedMemorySize, SMEM_TAIL);

    k_sqtau<<<B_N / 8, dim3(32, 8)>>>(x, Wt, bt);
    k_proj<<<dim3(H_N / 64, B_N / 64), 256>>>(x, Wp, bp);
    k_nn<<<dim3(B_N / 128, 2), 256, SMEM_NN>>>(x);
    k_merge<<<B_N / 256, 256>>>();
    k_tail<<<B_N / 16, 256, SMEM_TAIL>>>(Wr, br, lg, lb, Wf, bf, out);
}